// round 12
// baseline (speedup 1.0000x reference)
#include <cuda_runtime.h>
#include <math.h>

// Problem constants
#define BATCH 256
#define SEQLEN 512
#define OBS 64
#define NNEUR 1024
#define ACT 64
#define KTOT (NNEUR + OBS)
#define NBLK 256             // persistent CTAs: 2/SM on 148 SMs, all co-resident

#define BETA_C 0.9f
#define VTH_C 1.0f
#define STAGES 4             // cp.async pipeline depth (A1)

// ---------------- device scratch (static; no allocations) ----------------
__device__ float g_Wstk[KTOT * NNEUR];    // rows 0..1023: W_rec.T ; rows 1024..1087: W_in.T
__device__ float g_WoutT[NNEUR * ACT];    // (k, a)
__device__ float g_vA[BATCH * NNEUR];
__device__ float g_vB[BATCH * NNEUR];
__device__ float g_sA[BATCH * NNEUR];
__device__ float g_sB[BATCH * NNEUR];
__device__ unsigned g_count = 0;
__device__ unsigned g_sense = 0;          // monotonic phase; replay-safe

// ---------------- cp.async helpers ----------------
__device__ __forceinline__ void cp_async16(void* smem_dst, const void* gmem_src) {
    unsigned saddr = (unsigned)__cvta_generic_to_shared(smem_dst);
    asm volatile("cp.async.cg.shared.global [%0], [%1], 16;\n"
                 :: "r"(saddr), "l"(gmem_src));
}
__device__ __forceinline__ void cp_commit() {
    asm volatile("cp.async.commit_group;\n" ::: "memory");
}
template <int N>
__device__ __forceinline__ void cp_wait() {
    asm volatile("cp.async.wait_group %0;\n" :: "n"(N) : "memory");
}

// ---------------- software grid barrier (NBLK co-resident CTAs) ----------------
__device__ __forceinline__ void grid_barrier() {
    __syncthreads();
    if (threadIdx.x == 0) {
        unsigned s = *(volatile unsigned*)&g_sense;
        __threadfence();
        if (atomicAdd(&g_count, 1u) == NBLK - 1u) {
            g_count = 0;
            __threadfence();
            atomicExch(&g_sense, s + 1u);
        } else {
            while (*(volatile unsigned*)&g_sense == s) {}
        }
        __threadfence();
    }
    __syncthreads();
}

// ---------------- prep: tiled transpose into device scratch ----------------
__global__ void transpose_kernel(const float* __restrict__ src, int dst_sel,
                                 int rows, int cols) {
    float* dst = (dst_sel == 0) ? g_Wstk
               : (dst_sel == 1) ? (g_Wstk + NNEUR * NNEUR)
                                : g_WoutT;
    __shared__ float tile[32][33];
    int x = blockIdx.x * 32 + threadIdx.x;
    int y0 = blockIdx.y * 32;
#pragma unroll
    for (int j = 0; j < 32; j += 8) {
        int y = y0 + threadIdx.y + j;
        if (x < cols && y < rows)
            tile[threadIdx.y + j][threadIdx.x] = src[(size_t)y * cols + x];
    }
    __syncthreads();
    int xo = blockIdx.y * 32 + threadIdx.x;
    int yo0 = blockIdx.x * 32;
#pragma unroll
    for (int j = 0; j < 32; j += 8) {
        int yo = yo0 + threadIdx.y + j;
        if (xo < rows && yo < cols)
            dst[(size_t)yo * rows + xo] = tile[threadIdx.x][threadIdx.y + j];
    }
}

__global__ void zero_state_kernel() {
    int idx = blockIdx.x * blockDim.x + threadIdx.x;
    if (idx < BATCH * NNEUR) {
        g_vA[idx] = 0.0f;
        g_sA[idx] = 0.0f;
    }
}

__global__ void nop_kernel() {}

// ---------------- persistent time-loop kernel ----------------
// FROZEN numerics contract for the FEEDBACK path (bitwise-matched to ref):
//  * recurrent sum: split-K(2): k=[0,512),[512,1024), each ascending FMA
//    chain; combined P0 + P1 with one __fadd_rn.
//  * input projection: single ascending k=0..63 FMA chain.
//  * state update, no contraction: v' = (((0.9f*v) + accR) + accI) - s.
//  * spike: s' = (v' > 1.0f).  State reads via __ldcg (L2-coherent).
// This round changes DATA MOVEMENT ONLY (cp.async 4-stage pipeline for B,
// 3-ahead register pipeline for A); per-element accumulation order identical.
__global__ __launch_bounds__(128, 2) void lif_persistent(
        const float* __restrict__ inputs, float* __restrict__ out) {
    __shared__ float As[STAGES][16][36];   // [stage][kk][b]  32 batches
    __shared__ float Bs[STAGES][16][36];   // [stage][kk][i]  32 neurons
    __shared__ float sv[2][NNEUR];         // out-phase v rows
    __shared__ float red[2][2][ACT];       // out-phase partials

    const int tid = threadIdx.x;
    const int tx = tid & 7;             // neuron groups (TN=4) -> 32 i
    const int ty = tid >> 3;            // batch pairs  (TM=2) -> 32 b
    const int bi0 = (blockIdx.x & 31) * 32;   // 32 neuron tiles
    const int bb0 = (blockIdx.x >> 5) * 32;   // 8 batch tiles

    const int lb = tid >> 3;            // A: batch 0..15 (+16 second row)
    const int lk = (tid & 7) * 2;       // A: k pair
    const int wk = tid >> 3;            // B: k 0..15
    const int wi = (tid & 7) * 4;       // B: neuron quad

    const float* wB = &g_Wstk[(size_t)wk * NNEUR + bi0 + wi];  // k-step advance: 16*NNEUR

    for (int t = 0; t < SEQLEN; ++t) {
        const float* __restrict__ vIn  = (t & 1) ? g_vB : g_vA;
        float* __restrict__       vOut = (t & 1) ? g_vA : g_vB;
        const float* __restrict__ sIn  = (t & 1) ? g_sB : g_sA;
        float* __restrict__       sOut = (t & 1) ? g_sA : g_sB;

        const float* sRow0 = &sIn[(bb0 + lb) * NNEUR + lk];
        const float* sRow1 = &sIn[(bb0 + lb + 16) * NNEUR + lk];

        // ---- prologue: fill stages 0..2 ----
#pragma unroll
        for (int p = 0; p < 3; ++p) {
            float2 a0 = __ldcg(reinterpret_cast<const float2*>(sRow0 + p * 16));
            float2 a1 = __ldcg(reinterpret_cast<const float2*>(sRow1 + p * 16));
            As[p][lk][lb] = a0.x;       As[p][lk + 1][lb] = a0.y;
            As[p][lk][lb + 16] = a1.x;  As[p][lk + 1][lb + 16] = a1.y;
            cp_async16(&Bs[p][wk][wi], wB + (size_t)p * 16 * NNEUR);
            cp_commit();
        }

        // ======== phase A1: recurrent GEMM, 64 blocks, 4-stage pipeline ========
        float accP[2][4] = {{0.f,0.f,0.f,0.f},{0.f,0.f,0.f,0.f}};
        float accQ[2][4];
        float2 a0n, a1n;

        for (int blk = 0; blk < 64; ++blk) {
            const int st = blk & 3;
            cp_wait<2>();                 // B(blk) group retired
            __syncthreads();              // stage blk ready; stage (blk+3)&3 free
            const bool pf = (blk < 61);
            if (pf) {
                const int kn = (blk + 3) * 16;
                a0n = __ldcg(reinterpret_cast<const float2*>(sRow0 + kn));
                a1n = __ldcg(reinterpret_cast<const float2*>(sRow1 + kn));
                cp_async16(&Bs[(blk + 3) & 3][wk][wi], wB + (size_t)kn * NNEUR);
            }
            cp_commit();                  // exactly one group per iteration

            if (blk == 32) {              // split-K(2) boundary at k=512
#pragma unroll
                for (int m = 0; m < 2; ++m)
#pragma unroll
                    for (int n = 0; n < 4; ++n) {
                        accQ[m][n] = accP[m][n];
                        accP[m][n] = 0.0f;
                    }
            }
#pragma unroll
            for (int kk = 0; kk < 16; ++kk) {
                float2 a = *reinterpret_cast<const float2*>(&As[st][kk][ty * 2]);
                float4 b = *reinterpret_cast<const float4*>(&Bs[st][kk][tx * 4]);
                accP[0][0] = __fmaf_rn(a.x, b.x, accP[0][0]);
                accP[0][1] = __fmaf_rn(a.x, b.y, accP[0][1]);
                accP[0][2] = __fmaf_rn(a.x, b.z, accP[0][2]);
                accP[0][3] = __fmaf_rn(a.x, b.w, accP[0][3]);
                accP[1][0] = __fmaf_rn(a.y, b.x, accP[1][0]);
                accP[1][1] = __fmaf_rn(a.y, b.y, accP[1][1]);
                accP[1][2] = __fmaf_rn(a.y, b.z, accP[1][2]);
                accP[1][3] = __fmaf_rn(a.y, b.w, accP[1][3]);
            }
            if (pf) {
                const int sn = (blk + 3) & 3;
                As[sn][lk][lb] = a0n.x;       As[sn][lk + 1][lb] = a0n.y;
                As[sn][lk][lb + 16] = a1n.x;  As[sn][lk + 1][lb + 16] = a1n.y;
            }
        }
        float accS[2][4];
#pragma unroll
        for (int m = 0; m < 2; ++m)
#pragma unroll
            for (int n = 0; n < 4; ++n)
                accS[m][n] = __fadd_rn(accQ[m][n], accP[m][n]);  // P0 + P1

        // ======== phase A2: input projection (4 blocks, 2-stage registers) ========
        // stages 0/1 reused: last read at blk 60/61; all threads passed iter-63's
        // __syncthreads, so reuse is safe.
        float accI[2][4] = {{0.f,0.f,0.f,0.f},{0.f,0.f,0.f,0.f}};
        {
            const size_t ib0 = ((size_t)(bb0 + lb) * SEQLEN + t) * OBS;
            const size_t ib1 = ((size_t)(bb0 + lb + 16) * SEQLEN + t) * OBS;
            float2 av0 = *reinterpret_cast<const float2*>(&inputs[ib0 + lk]);
            float2 av1 = *reinterpret_cast<const float2*>(&inputs[ib1 + lk]);
            float4 bv = *reinterpret_cast<const float4*>(
                    &g_Wstk[(size_t)(NNEUR + wk) * NNEUR + bi0 + wi]);
            As[0][lk][lb] = av0.x;       As[0][lk + 1][lb] = av0.y;
            As[0][lk][lb + 16] = av1.x;  As[0][lk + 1][lb + 16] = av1.y;
            *reinterpret_cast<float4*>(&Bs[0][wk][wi]) = bv;
#pragma unroll
            for (int blk = 0; blk < 4; ++blk) {
                const int st = blk & 1;
                __syncthreads();
                if (blk < 3) {
                    const int kc = (blk + 1) * 16;
                    av0 = *reinterpret_cast<const float2*>(&inputs[ib0 + kc + lk]);
                    av1 = *reinterpret_cast<const float2*>(&inputs[ib1 + kc + lk]);
                    bv = *reinterpret_cast<const float4*>(
                            &g_Wstk[(size_t)(NNEUR + kc + wk) * NNEUR + bi0 + wi]);
                }
#pragma unroll
                for (int kk = 0; kk < 16; ++kk) {
                    float2 a = *reinterpret_cast<const float2*>(&As[st][kk][ty * 2]);
                    float4 b = *reinterpret_cast<const float4*>(&Bs[st][kk][tx * 4]);
                    accI[0][0] = __fmaf_rn(a.x, b.x, accI[0][0]);
                    accI[0][1] = __fmaf_rn(a.x, b.y, accI[0][1]);
                    accI[0][2] = __fmaf_rn(a.x, b.z, accI[0][2]);
                    accI[0][3] = __fmaf_rn(a.x, b.w, accI[0][3]);
                    accI[1][0] = __fmaf_rn(a.y, b.x, accI[1][0]);
                    accI[1][1] = __fmaf_rn(a.y, b.y, accI[1][1]);
                    accI[1][2] = __fmaf_rn(a.y, b.z, accI[1][2]);
                    accI[1][3] = __fmaf_rn(a.y, b.w, accI[1][3]);
                }
                if (blk < 3) {
                    const int sn = st ^ 1;
                    As[sn][lk][lb] = av0.x;       As[sn][lk + 1][lb] = av0.y;
                    As[sn][lk][lb + 16] = av1.x;  As[sn][lk + 1][lb + 16] = av1.y;
                    *reinterpret_cast<float4*>(&Bs[sn][wk][wi]) = bv;
                }
            }
        }

        // ---- epilogue: v' = (((0.9*v) + accS) + accI) - s  — strictly NO fma ----
#pragma unroll
        for (int m = 0; m < 2; ++m) {
            int b = bb0 + ty * 2 + m;
#pragma unroll
            for (int n = 0; n < 4; ++n) {
                int i = bi0 + tx * 4 + n;
                int idx = b * NNEUR + i;
                float so = __ldcg(&sIn[idx]);
                float vl = __ldcg(&vIn[idx]);
                float leak = __fmul_rn(BETA_C, vl);
                float v = __fsub_rn(
                            __fadd_rn(__fadd_rn(leak, accS[m][n]), accI[m][n]),
                            so);
                vOut[idx] = v;
                sOut[idx] = (v > VTH_C) ? 1.0f : 0.0f;
            }
        }

        grid_barrier();

        // ======== phase B: action head on CTAs 0..127 (2 rows each) ========
        // Non-feedback -> free ordering. CTAs 128..255 proceed straight to the
        // next step's GEMM (opposite-parity state buffers; no hazard).
        if (blockIdx.x < 128) {
            const int r0 = blockIdx.x * 2;
            const float4* vs = reinterpret_cast<const float4*>(&vOut[(size_t)r0 * NNEUR]);
            float4* dstv = reinterpret_cast<float4*>(&sv[0][0]);
#pragma unroll
            for (int i = 0; i < 4; ++i)
                dstv[tid + i * 128] = __ldcg(&vs[tid + i * 128]);
            __syncthreads();

            const int a = tid & 63;
            const int h = tid >> 6;             // k-half
            const int kb = h * 512;
            float x0 = 0.f, x1 = 0.f;
#pragma unroll 8
            for (int k = 0; k < 512; ++k) {
                float w = g_WoutT[(size_t)(kb + k) * ACT + a];
                x0 = __fmaf_rn(sv[0][kb + k], w, x0);
                x1 = __fmaf_rn(sv[1][kb + k], w, x1);
            }
            red[h][0][a] = x0;
            red[h][1][a] = x1;
            __syncthreads();

            const int rr = tid >> 6;            // row 0/1
            const int aa = tid & 63;
            float s2 = __fadd_rn(red[0][rr][aa], red[1][rr][aa]);
            out[((size_t)(r0 + rr) * SEQLEN + t) * ACT + aa] = tanhf(s2);
            // sv/red reused only after the NEXT grid_barrier + __syncthreads.
        }
    }
}

// ---------------- launch ----------------
extern "C" void kernel_launch(void* const* d_in, const int* in_sizes, int n_in,
                              void* d_out, int out_size) {
    const float* inputs = (const float*)d_in[0];   // (B, T, OBS)
    const float* W_rec  = (const float*)d_in[1];   // (N, N)
    const float* W_in   = (const float*)d_in[2];   // (N, OBS)
    const float* W_out  = (const float*)d_in[3];   // (ACT, N)
    float* out = (float*)d_out;                    // (B, T, ACT)

    dim3 tb(32, 8);
    transpose_kernel<<<dim3(NNEUR / 32, NNEUR / 32), tb>>>(W_rec, 0, NNEUR, NNEUR);
    transpose_kernel<<<dim3(OBS / 32, NNEUR / 32), tb>>>(W_in, 1, NNEUR, OBS);
    transpose_kernel<<<dim3(NNEUR / 32, ACT / 32), tb>>>(W_out, 2, ACT, NNEUR);
    zero_state_kernel<<<(BATCH * NNEUR) / 256, 256>>>();
    nop_kernel<<<1, 32>>>();

    lif_persistent<<<NBLK, 128>>>(inputs, out);
}